// round 16
// baseline (speedup 1.0000x reference)
#include <cuda_runtime.h>
#include <cuda_bf16.h>
#include <math.h>
#include <cstdint>

// ---------------------------------------------------------------------------
// VectorQuantizer forward (sm_103 portable ISA)
//   bf16 HMMA screening GEMM (legacy-HMMA floor; inline f32->bf16 A) with
//   IN-GRID overlapped rescore blocks (flag-gated), 1-kernel rescue, finalize
// ---------------------------------------------------------------------------

#define B_ROWS   32768
#define K_CODES  4096
#define DIM      256
#define ZQ_ELEMS (B_ROWS * DIM)
#define SCAL_OFF ZQ_ELEMS
#define IDX_OFF  (ZQ_ELEMS + 5)
#define NTILES   32
#define MARGIN   0.05f
#define MAX_CAND 16
#define MAX_AMBIG 4096
#define GEMM_BLOCKS 256
#define RESC_BLOCKS 1024

// ------------------------- device scratch (static) -------------------------
__device__ __align__(16) __nv_bfloat16 g_cbhi[K_CODES * DIM];
__device__ __align__(16) float g_cbn[K_CODES * DIM];     // normalized fp32
__device__ int    g_idx[B_ROWS];
__device__ int    g_counts[K_CODES];
__device__ double g_partials[1024];
__device__ int    g_ccnt[B_ROWS];
__device__ int    g_cand[B_ROWS * MAX_CAND];
__device__ int    g_ambig_n;
__device__ int    g_ambig[MAX_AMBIG];
__device__ int    g_done[GEMM_BLOCKS];

// ------------------------- helpers -----------------------------------------
__device__ __forceinline__ uint32_t smem_u32(const void* p) {
    uint32_t a;
    asm("{ .reg .u64 t; cvta.to.shared.u64 t, %1; cvt.u32.u64 %0, t; }"
        : "=r"(a) : "l"(p));
    return a;
}
__device__ __forceinline__ void cp_async16(uint32_t dst, const void* src) {
    asm volatile("cp.async.cg.shared.global [%0], [%1], 16;"
                 :: "r"(dst), "l"(src) : "memory");
}
#define CP_COMMIT() asm volatile("cp.async.commit_group;" ::: "memory")

__device__ __forceinline__ void ldm_x4(uint32_t& r0, uint32_t& r1,
                                       uint32_t& r2, uint32_t& r3, uint32_t addr) {
    asm volatile("ldmatrix.sync.aligned.m8n8.x4.shared.b16 {%0,%1,%2,%3}, [%4];"
                 : "=r"(r0), "=r"(r1), "=r"(r2), "=r"(r3) : "r"(addr));
}
__device__ __forceinline__ void mma16816(float* d, const uint32_t* a,
                                         uint32_t b0, uint32_t b1) {
    asm volatile("mma.sync.aligned.m16n8k16.row.col.f32.bf16.bf16.f32 "
                 "{%0,%1,%2,%3}, {%4,%5,%6,%7}, {%8,%9}, {%0,%1,%2,%3};"
                 : "+f"(d[0]), "+f"(d[1]), "+f"(d[2]), "+f"(d[3])
                 : "r"(a[0]), "r"(a[1]), "r"(a[2]), "r"(a[3]), "r"(b0), "r"(b1));
}
__device__ __forceinline__ bool better(float va, int ia, float vb, int ib) {
    return (va > vb) || (va == vb && ia < ib);
}
__device__ __forceinline__ uint32_t fenc(float f) {
    uint32_t b = __float_as_uint(f);
    return (b & 0x80000000u) ? ~b : (b | 0x80000000u);
}
__device__ __forceinline__ float fdec(uint32_t k) {
    uint32_t b = (k & 0x80000000u) ? (k & 0x7FFFFFFFu) : ~k;
    return __uint_as_float(b);
}
__device__ __forceinline__ uint32_t pack_bf2(float a, float b) {
    __nv_bfloat162 h = __floats2bfloat162_rn(a, b);
    return *(uint32_t*)&h;
}

// ------------------------- K1: prep (cb norm + zero stats) -----------------
// blocks [0,4096): cb norm ; [4096,4113): zero stats + flags
__global__ void vq_prep(const float* __restrict__ cb) {
    const int b = blockIdx.x;
    const int t = threadIdx.x;
    if (b < 4096) {
        int row = b;
        float v = cb[(size_t)row * DIM + t];
        __shared__ float red[256];
        red[t] = v * v;
        __syncthreads();
        for (int s = 128; s > 0; s >>= 1) {
            if (t < s) red[t] += red[t + s];
            __syncthreads();
        }
        float r = 1.0f / fmaxf(sqrtf(red[0]), 1e-12f);
        float val = v * r;
        g_cbn[(size_t)row * DIM + t]  = val;
        g_cbhi[(size_t)row * DIM + t] = __float2bfloat16(val);
    } else {
        int i = (b - 4096) * 256 + t;
        if (i < K_CODES) g_counts[i] = 0;
        if (i < 1024)    g_partials[i] = 0.0;
        if (i < GEMM_BLOCKS) g_done[i] = 0;
        if (i == 0)      g_ambig_n = 0;
    }
}

// --------- K2: GEMM blocks [0,256) + overlapped rescore blocks [256,1280) --
#define AS_BYTES  65536u
#define BS_BYTES  16384u
#define RM_OFF    98304u      // rowmax[128] uint
#define CNT_OFF   98816u      // cnt[128] int
#define CAND_OFF  99328u      // cand[128][16] int
#define SMEM_TOT  107520u

__global__ void __launch_bounds__(128, 2)
vq_main(const float* __restrict__ x, float* __restrict__ out, int out_size) {
    extern __shared__ __align__(1024) char smem[];
    const int tid  = threadIdx.x;
    const int lane = tid & 31;
    const int wid  = tid >> 5;

    if (blockIdx.x < GEMM_BLOCKS) {
        // =================== GEMM + candidate screening =====================
        const uint32_t as_base = smem_u32(smem);
        const uint32_t bs_base = as_base + AS_BYTES;
        uint32_t* rowmax = (uint32_t*)(smem + RM_OFF);
        int*      cnt    = (int*)(smem + CNT_OFF);
        int*      cand   = (int*)(smem + CAND_OFF);

        const int warpM = wid >> 1;
        const int warpN = wid & 1;
        const int m0    = blockIdx.x * 128;

        rowmax[tid] = 0u; cnt[tid] = 0;

        auto loadB = [&](uint32_t bufb, int j) {
            const int nt = j >> 2, c = j & 3;
            const char* srcb = (const char*)g_cbhi +
                               ((size_t)nt * 128 * DIM + c * 64) * 2;
#pragma unroll
            for (int i = 0; i < 8; i++) {
                int u = tid + i * 128;
                int r = u >> 3, c16 = u & 7;
                uint32_t dst = bufb + r * 128 + ((c16 ^ (r & 7)) << 4);
                cp_async16(dst, srcb + (size_t)r * DIM * 2 + c16 * 16);
            }
            CP_COMMIT();
        };
        loadB(bs_base, 0);

        // A: load f32 rows, convert to bf16, store swizzled
#pragma unroll 4
        for (int i = 0; i < 32; i++) {
            int u = tid + i * 128;
            int r = u >> 5, c16 = u & 31;
            const float4* src = (const float4*)(x + (size_t)(m0 + r) * DIM + c16 * 8);
            float4 v0 = src[0];
            float4 v1 = src[1];
            uint4 pk;
            pk.x = pack_bf2(v0.x, v0.y);
            pk.y = pack_bf2(v0.z, v0.w);
            pk.z = pack_bf2(v1.x, v1.y);
            pk.w = pack_bf2(v1.z, v1.w);
            uint32_t off = (uint32_t)r * 512 + (((uint32_t)c16 ^ (r & 7)) << 4);
            *(uint4*)(smem + off) = pk;
        }

        uint32_t aoff[4]; int asw[4];
#pragma unroll
        for (int mf = 0; mf < 4; mf++) {
            int arow = warpM * 64 + mf * 16 + (lane & 15);
            aoff[mf] = as_base + arow * 512;
            asw[mf]  = arow & 7;
        }
        const int ahalf = (lane >> 4) & 1;
        uint32_t boff[4]; int bsw[4];
#pragma unroll
        for (int p = 0; p < 4; p++) {
            int code = warpN * 64 + p * 16 + ((lane >> 4) & 1) * 8 + (lane & 7);
            boff[p] = code * 128;
            bsw[p]  = code & 7;
        }
        const int bku = (lane >> 3) & 1;

        float acc[4][8][4];
#pragma unroll
        for (int i = 0; i < 4; i++)
#pragma unroll
            for (int j = 0; j < 8; j++)
#pragma unroll
                for (int k = 0; k < 4; k++) acc[i][j][k] = 0.0f;

        for (int j = 0; j < 4 * NTILES; j++) {
            if (j + 1 < 4 * NTILES) {
                loadB(bs_base + ((j + 1) & 1) * BS_BYTES, j + 1);
                asm volatile("cp.async.wait_group 1;" ::: "memory");
            } else {
                asm volatile("cp.async.wait_group 0;" ::: "memory");
            }
            __syncthreads();

            const uint32_t buf = bs_base + (j & 1) * BS_BYTES;
            const int c = j & 3;
#pragma unroll
            for (int k16 = 0; k16 < 4; k16++) {
                const int kk = k16 * 16;
                uint32_t b[8][2];
#pragma unroll
                for (int p = 0; p < 4; p++) {
                    uint32_t addr = buf + boff[p] + ((((kk >> 3) + bku) ^ bsw[p]) << 4);
                    ldm_x4(b[2 * p][0], b[2 * p][1], b[2 * p + 1][0], b[2 * p + 1][1], addr);
                }
                uint32_t a[4][4];
                const int uab = c * 8 + k16 * 2 + ahalf;
#pragma unroll
                for (int mf = 0; mf < 4; mf++) {
                    uint32_t addr = aoff[mf] + ((uab ^ asw[mf]) << 4);
                    ldm_x4(a[mf][0], a[mf][1], a[mf][2], a[mf][3], addr);
                }
#pragma unroll
                for (int mf = 0; mf < 4; mf++)
#pragma unroll
                    for (int nf = 0; nf < 8; nf++)
                        mma16816(acc[mf][nf], a[mf], b[nf][0], b[nf][1]);
            }

            if (c == 3) {
                const int nt = j >> 2;
#pragma unroll
                for (int mf = 0; mf < 4; mf++)
#pragma unroll
                    for (int h = 0; h < 2; h++) {
                        int r = warpM * 64 + mf * 16 + h * 8 + (lane >> 2);
                        float m = fmaxf(acc[mf][0][2 * h], acc[mf][0][2 * h + 1]);
#pragma unroll
                        for (int nf = 1; nf < 8; nf++)
                            m = fmaxf(m, fmaxf(acc[mf][nf][2 * h], acc[mf][nf][2 * h + 1]));
                        m = fmaxf(m, __shfl_xor_sync(0xFFFFFFFFu, m, 1));
                        m = fmaxf(m, __shfl_xor_sync(0xFFFFFFFFu, m, 2));
                        if ((lane & 3) == 0) atomicMax(&rowmax[r], fenc(m));
                    }
                __syncthreads();
#pragma unroll
                for (int mf = 0; mf < 4; mf++)
#pragma unroll
                    for (int h = 0; h < 2; h++) {
                        int r = warpM * 64 + mf * 16 + h * 8 + (lane >> 2);
                        float thr = fdec(rowmax[r]) - MARGIN;
#pragma unroll
                        for (int nf = 0; nf < 8; nf++) {
                            int cb0 = nt * 128 + warpN * 64 + nf * 8 + (lane & 3) * 2;
                            float va = acc[mf][nf][2 * h], vb = acc[mf][nf][2 * h + 1];
                            if (va >= thr) {
                                int p = atomicAdd(&cnt[r], 1);
                                if (p < MAX_CAND) cand[r * MAX_CAND + p] = cb0;
                            }
                            if (vb >= thr) {
                                int p = atomicAdd(&cnt[r], 1);
                                if (p < MAX_CAND) cand[r * MAX_CAND + p] = cb0 + 1;
                            }
                        }
                    }
#pragma unroll
                for (int i = 0; i < 4; i++)
#pragma unroll
                    for (int jj = 0; jj < 8; jj++)
#pragma unroll
                        for (int k = 0; k < 4; k++) acc[i][jj][k] = 0.0f;
            }
            __syncthreads();
        }

        // flush candidate lists, then release flag
        {
            int row = m0 + tid;
            int c = cnt[tid];
            g_ccnt[row] = c;
            int n = c < MAX_CAND ? c : MAX_CAND;
            for (int i = 0; i < n; i++) g_cand[row * MAX_CAND + i] = cand[tid * MAX_CAND + i];
            if (c > MAX_CAND) {
                int p = atomicAdd(&g_ambig_n, 1);
                if (p < MAX_AMBIG) g_ambig[p] = row;
            }
        }
        __syncthreads();
        __threadfence();
        if (tid == 0) atomicExch(&g_done[blockIdx.x], 1);
    } else {
        // =================== overlapped rescore blocks ======================
        const int bid2 = blockIdx.x - GEMM_BLOCKS;      // 0..1023
        const int fb   = bid2 >> 2;                     // producing GEMM CTA
        const bool write_idx = (out_size >= IDX_OFF + B_ROWS);
        __shared__ double wpart[4];

        if (tid == 0) {
            while (atomicAdd(&g_done[fb], 0) == 0) __nanosleep(256);
        }
        __syncthreads();
        __threadfence();

        double dsum = 0.0;
#pragma unroll 1
        for (int i = 0; i < 8; i++) {
            int row = (bid2 * 4 + wid) * 8 + i;
            int c = g_ccnt[row];
            if (c > MAX_CAND) continue;          // rescue path owns this row
            float xv[8];
#pragma unroll
            for (int jj = 0; jj < 8; jj++) xv[jj] = x[(size_t)row * DIM + lane + jj * 32];
            int bi;
            if (c == 1) {
                bi = g_cand[row * MAX_CAND];
            } else {
                float bv = -3.0e38f; bi = 0x7FFFFFFF;
                for (int k = 0; k < c; k++) {
                    int code = g_cand[row * MAX_CAND + k];
                    const float* cr = g_cbn + (size_t)code * DIM;
                    float s = 0.0f;
#pragma unroll
                    for (int jj = 0; jj < 8; jj++) s = fmaf(xv[jj], cr[lane + jj * 32], s);
#pragma unroll
                    for (int m = 16; m > 0; m >>= 1) s += __shfl_xor_sync(0xFFFFFFFFu, s, m);
                    if (better(s, code, bv, bi)) { bv = s; bi = code; }
                }
            }
            const float* cw = g_cbn + (size_t)bi * DIM;
            float ls = 0.0f;
#pragma unroll
            for (int jj = 0; jj < 8; jj++) {
                float cv = cw[lane + jj * 32];
                float xx = xv[jj];
                out[(size_t)row * DIM + lane + jj * 32] = xx + (cv - xx);
                float d = xx - cv;
                ls = fmaf(d, d, ls);
            }
            dsum += (double)ls;
            if (lane == 0) {
                g_idx[row] = bi;
                atomicAdd(&g_counts[bi], 1);
                if (write_idx) out[IDX_OFF + row] = (float)bi;
            }
        }
#pragma unroll
        for (int m = 16; m > 0; m >>= 1) dsum += __shfl_xor_sync(0xFFFFFFFFu, dsum, m);
        if (lane == 0) wpart[wid] = dsum;
        __syncthreads();
        if (tid == 0) {
            double s = (wpart[0] + wpart[1]) + (wpart[2] + wpart[3]);
            g_partials[bid2] = s;
        }
    }
}

// ------------- K3: single-kernel fallback full scan (overflow rows) --------
__global__ void vq_rescue(const float* __restrict__ x, float* __restrict__ out,
                          int out_size) {
    const int t = threadIdx.x;
    int n = g_ambig_n; if (n > MAX_AMBIG) n = MAX_AMBIG;
    __shared__ float  xs[256];
    __shared__ float  bvs[256];
    __shared__ int    bis[256];
    __shared__ double dred[256];

    for (int fi = blockIdx.x; fi < n; fi += 64) {
        int row = g_ambig[fi];
        xs[t] = x[(size_t)row * DIM + t];
        __syncthreads();
        float bv = -3.0e38f; int bi = 0x7FFFFFFF;
        for (int code = t; code < K_CODES; code += 256) {
            const float* cr = g_cbn + (size_t)code * DIM;
            float s = 0.0f;
#pragma unroll 8
            for (int d = 0; d < DIM; d++) s = fmaf(xs[d], cr[d], s);
            if (better(s, code, bv, bi)) { bv = s; bi = code; }
        }
        bvs[t] = bv; bis[t] = bi;
        __syncthreads();
        for (int s2 = 128; s2 > 0; s2 >>= 1) {
            if (t < s2 && better(bvs[t + s2], bis[t + s2], bvs[t], bis[t])) {
                bvs[t] = bvs[t + s2]; bis[t] = bis[t + s2];
            }
            __syncthreads();
        }
        bi = bis[0];
        if (t == 0) {
            g_idx[row] = bi;
            atomicAdd(&g_counts[bi], 1);
            if (out_size >= IDX_OFF + B_ROWS) out[IDX_OFF + row] = (float)bi;
        }
        float xx = xs[t];
        float cv = g_cbn[(size_t)bi * DIM + t];
        out[(size_t)row * DIM + t] = xx + (cv - xx);
        float d = xx - cv;
        dred[t] = (double)d * (double)d;
        __syncthreads();
        for (int s2 = 128; s2 > 0; s2 >>= 1) {
            if (t < s2) dred[t] += dred[t + s2];
            __syncthreads();
        }
        if (t == 0) atomicAdd(&g_partials[512 + (fi & 511)], dred[0]);
        __syncthreads();
    }
}

// ------------------------- K4: finalize (scalars only) ---------------------
__global__ void vq_finalize(float* __restrict__ out, int out_size) {
    const int t = threadIdx.x;
    __shared__ double sred[256];
    sred[t] = g_partials[t] + g_partials[t + 256] + g_partials[t + 512] + g_partials[t + 768];
    __syncthreads();
    for (int s = 128; s > 0; s >>= 1) {
        if (t < s) sred[t] += sred[t + s];
        __syncthreads();
    }
    double q = sred[0] / (double)ZQ_ELEMS;
    __syncthreads();

    double h = 0.0;
    for (int k = t; k < K_CODES; k += 256) {
        int c = g_counts[k];
        if (c > 0) {
            double p = (double)c / (double)B_ROWS;
            h -= p * log(p);
        }
    }
    sred[t] = h;
    __syncthreads();
    for (int s = 128; s > 0; s >>= 1) {
        if (t < s) sred[t] += sred[t + s];
        __syncthreads();
    }
    double H = sred[0];

    if (t == 0 && out_size >= SCAL_OFF + 5) {
        out[SCAL_OFF + 0] = (float)(1.25 * q - 0.1 * H);
        out[SCAL_OFF + 1] = (float)q;
        out[SCAL_OFF + 2] = (float)q;
        out[SCAL_OFF + 3] = (float)(-H);
        out[SCAL_OFF + 4] = (float)H;
    }
}

// ------------------------- launch ------------------------------------------
extern "C" void kernel_launch(void* const* d_in, const int* in_sizes, int n_in,
                              void* d_out, int out_size) {
    const float* x  = (const float*)d_in[0];
    const float* cb = (const float*)d_in[1];
    if (n_in >= 2 && in_sizes[0] == K_CODES * DIM && in_sizes[1] == B_ROWS * DIM) {
        x  = (const float*)d_in[1];
        cb = (const float*)d_in[0];
    }
    float* out = (float*)d_out;

    static bool attr_set = false;
    if (!attr_set) {
        cudaFuncSetAttribute(vq_main,
                             cudaFuncAttributeMaxDynamicSharedMemorySize,
                             (int)SMEM_TOT);
        attr_set = true;
    }

    vq_prep<<<4113, 256>>>(cb);
    vq_main<<<GEMM_BLOCKS + RESC_BLOCKS, 128, SMEM_TOT>>>(x, out, out_size);
    vq_rescue<<<64, 256>>>(x, out, out_size);
    vq_finalize<<<1, 256>>>(out, out_size);
}

// round 17
// speedup vs baseline: 1.2999x; 1.2999x over previous
#include <cuda_runtime.h>
#include <cuda_bf16.h>
#include <math.h>
#include <cstdint>

// ---------------------------------------------------------------------------
// VectorQuantizer forward (sm_103 portable ISA)
//   bf16 HMMA screening GEMM (legacy-HMMA floor; inline f32->bf16 A)
//   + fused rescore (z_q, losses, histogram, index tail) + 1-kernel rescue
//   + fast fp32-log finalize
// ---------------------------------------------------------------------------

#define B_ROWS   32768
#define K_CODES  4096
#define DIM      256
#define ZQ_ELEMS (B_ROWS * DIM)
#define SCAL_OFF ZQ_ELEMS
#define IDX_OFF  (ZQ_ELEMS + 5)
#define NTILES   32
#define MARGIN   0.05f
#define MAX_CAND 16
#define MAX_AMBIG 4096

// ------------------------- device scratch (static) -------------------------
__device__ __align__(16) __nv_bfloat16 g_cbhi[K_CODES * DIM];
__device__ __align__(16) float g_cbn[K_CODES * DIM];     // normalized fp32
__device__ int    g_idx[B_ROWS];
__device__ int    g_counts[K_CODES];
__device__ double g_partials[1024];
__device__ int    g_ccnt[B_ROWS];
__device__ int    g_cand[B_ROWS * MAX_CAND];
__device__ int    g_ambig_n;
__device__ int    g_ambig[MAX_AMBIG];

// ------------------------- helpers -----------------------------------------
__device__ __forceinline__ uint32_t smem_u32(const void* p) {
    uint32_t a;
    asm("{ .reg .u64 t; cvta.to.shared.u64 t, %1; cvt.u32.u64 %0, t; }"
        : "=r"(a) : "l"(p));
    return a;
}
__device__ __forceinline__ void cp_async16(uint32_t dst, const void* src) {
    asm volatile("cp.async.cg.shared.global [%0], [%1], 16;"
                 :: "r"(dst), "l"(src) : "memory");
}
#define CP_COMMIT() asm volatile("cp.async.commit_group;" ::: "memory")

__device__ __forceinline__ void ldm_x4(uint32_t& r0, uint32_t& r1,
                                       uint32_t& r2, uint32_t& r3, uint32_t addr) {
    asm volatile("ldmatrix.sync.aligned.m8n8.x4.shared.b16 {%0,%1,%2,%3}, [%4];"
                 : "=r"(r0), "=r"(r1), "=r"(r2), "=r"(r3) : "r"(addr));
}
__device__ __forceinline__ void mma16816(float* d, const uint32_t* a,
                                         uint32_t b0, uint32_t b1) {
    asm volatile("mma.sync.aligned.m16n8k16.row.col.f32.bf16.bf16.f32 "
                 "{%0,%1,%2,%3}, {%4,%5,%6,%7}, {%8,%9}, {%0,%1,%2,%3};"
                 : "+f"(d[0]), "+f"(d[1]), "+f"(d[2]), "+f"(d[3])
                 : "r"(a[0]), "r"(a[1]), "r"(a[2]), "r"(a[3]), "r"(b0), "r"(b1));
}
__device__ __forceinline__ bool better(float va, int ia, float vb, int ib) {
    return (va > vb) || (va == vb && ia < ib);
}
__device__ __forceinline__ uint32_t fenc(float f) {
    uint32_t b = __float_as_uint(f);
    return (b & 0x80000000u) ? ~b : (b | 0x80000000u);
}
__device__ __forceinline__ float fdec(uint32_t k) {
    uint32_t b = (k & 0x80000000u) ? (k & 0x7FFFFFFFu) : ~k;
    return __uint_as_float(b);
}
__device__ __forceinline__ uint32_t pack_bf2(float a, float b) {
    __nv_bfloat162 h = __floats2bfloat162_rn(a, b);
    return *(uint32_t*)&h;
}

// ------------------------- K1: prep (cb norm + zero stats) -----------------
// blocks [0,4096): cb norm ; [4096,4112): zero stats
__global__ void vq_prep(const float* __restrict__ cb) {
    const int b = blockIdx.x;
    const int t = threadIdx.x;
    if (b < 4096) {
        int row = b;
        float v = cb[(size_t)row * DIM + t];
        __shared__ float red[256];
        red[t] = v * v;
        __syncthreads();
        for (int s = 128; s > 0; s >>= 1) {
            if (t < s) red[t] += red[t + s];
            __syncthreads();
        }
        float r = 1.0f / fmaxf(sqrtf(red[0]), 1e-12f);
        float val = v * r;
        g_cbn[(size_t)row * DIM + t]  = val;
        g_cbhi[(size_t)row * DIM + t] = __float2bfloat16(val);
    } else {
        int i = (b - 4096) * 256 + t;
        if (i < K_CODES) g_counts[i] = 0;
        if (i < 1024)    g_partials[i] = 0.0;
        if (i == 0)      g_ambig_n = 0;
    }
}

// ------------------------- K2: screening GEMM + candidates -----------------
#define AS_BYTES  65536u
#define BS_BYTES  16384u
#define RM_OFF    98304u      // rowmax[128] uint
#define CNT_OFF   98816u      // cnt[128] int
#define CAND_OFF  99328u      // cand[128][16] int
#define SMEM_TOT  107520u

__global__ void __launch_bounds__(128, 2)
vq_mma_argmax(const float* __restrict__ x) {
    extern __shared__ __align__(1024) char smem[];
    const uint32_t as_base = smem_u32(smem);
    const uint32_t bs_base = as_base + AS_BYTES;
    uint32_t* rowmax = (uint32_t*)(smem + RM_OFF);
    int*      cnt    = (int*)(smem + CNT_OFF);
    int*      cand   = (int*)(smem + CAND_OFF);

    const int tid   = threadIdx.x;
    const int lane  = tid & 31;
    const int wid   = tid >> 5;
    const int warpM = wid >> 1;
    const int warpN = wid & 1;
    const int m0    = blockIdx.x * 128;

    rowmax[tid] = 0u; cnt[tid] = 0;

    auto loadB = [&](uint32_t bufb, int j) {
        const int nt = j >> 2, c = j & 3;
        const char* srcb = (const char*)g_cbhi +
                           ((size_t)nt * 128 * DIM + c * 64) * 2;
#pragma unroll
        for (int i = 0; i < 8; i++) {
            int u = tid + i * 128;
            int r = u >> 3, c16 = u & 7;
            uint32_t dst = bufb + r * 128 + ((c16 ^ (r & 7)) << 4);
            cp_async16(dst, srcb + (size_t)r * DIM * 2 + c16 * 16);
        }
        CP_COMMIT();
    };
    loadB(bs_base, 0);   // start B chunk 0 first (async)

    // A: load f32 x rows, convert to bf16, store swizzled (overlaps B load)
#pragma unroll 4
    for (int i = 0; i < 32; i++) {
        int u = tid + i * 128;
        int r = u >> 5, c16 = u & 31;
        const float4* src = (const float4*)(x + (size_t)(m0 + r) * DIM + c16 * 8);
        float4 v0 = src[0];
        float4 v1 = src[1];
        uint4 pk;
        pk.x = pack_bf2(v0.x, v0.y);
        pk.y = pack_bf2(v0.z, v0.w);
        pk.z = pack_bf2(v1.x, v1.y);
        pk.w = pack_bf2(v1.z, v1.w);
        uint32_t off = (uint32_t)r * 512 + (((uint32_t)c16 ^ (r & 7)) << 4);
        *(uint4*)(smem + off) = pk;
    }

    uint32_t aoff[4]; int asw[4];
#pragma unroll
    for (int mf = 0; mf < 4; mf++) {
        int arow = warpM * 64 + mf * 16 + (lane & 15);
        aoff[mf] = as_base + arow * 512;
        asw[mf]  = arow & 7;
    }
    const int ahalf = (lane >> 4) & 1;
    uint32_t boff[4]; int bsw[4];
#pragma unroll
    for (int p = 0; p < 4; p++) {
        int code = warpN * 64 + p * 16 + ((lane >> 4) & 1) * 8 + (lane & 7);
        boff[p] = code * 128;
        bsw[p]  = code & 7;
    }
    const int bku = (lane >> 3) & 1;

    float acc[4][8][4];
#pragma unroll
    for (int i = 0; i < 4; i++)
#pragma unroll
        for (int j = 0; j < 8; j++)
#pragma unroll
            for (int k = 0; k < 4; k++) acc[i][j][k] = 0.0f;

    for (int j = 0; j < 4 * NTILES; j++) {
        if (j + 1 < 4 * NTILES) {
            loadB(bs_base + ((j + 1) & 1) * BS_BYTES, j + 1);
            asm volatile("cp.async.wait_group 1;" ::: "memory");
        } else {
            asm volatile("cp.async.wait_group 0;" ::: "memory");
        }
        __syncthreads();

        const uint32_t buf = bs_base + (j & 1) * BS_BYTES;
        const int c = j & 3;
#pragma unroll
        for (int k16 = 0; k16 < 4; k16++) {
            const int kk = k16 * 16;
            uint32_t b[8][2];
#pragma unroll
            for (int p = 0; p < 4; p++) {
                uint32_t addr = buf + boff[p] + ((((kk >> 3) + bku) ^ bsw[p]) << 4);
                ldm_x4(b[2 * p][0], b[2 * p][1], b[2 * p + 1][0], b[2 * p + 1][1], addr);
            }
            uint32_t a[4][4];
            const int uab = c * 8 + k16 * 2 + ahalf;
#pragma unroll
            for (int mf = 0; mf < 4; mf++) {
                uint32_t addr = aoff[mf] + ((uab ^ asw[mf]) << 4);
                ldm_x4(a[mf][0], a[mf][1], a[mf][2], a[mf][3], addr);
            }
#pragma unroll
            for (int mf = 0; mf < 4; mf++)
#pragma unroll
                for (int nf = 0; nf < 8; nf++)
                    mma16816(acc[mf][nf], a[mf], b[nf][0], b[nf][1]);
        }

        if (c == 3) {
            const int nt = j >> 2;
#pragma unroll
            for (int mf = 0; mf < 4; mf++)
#pragma unroll
                for (int h = 0; h < 2; h++) {
                    int r = warpM * 64 + mf * 16 + h * 8 + (lane >> 2);
                    float m = fmaxf(acc[mf][0][2 * h], acc[mf][0][2 * h + 1]);
#pragma unroll
                    for (int nf = 1; nf < 8; nf++)
                        m = fmaxf(m, fmaxf(acc[mf][nf][2 * h], acc[mf][nf][2 * h + 1]));
                    m = fmaxf(m, __shfl_xor_sync(0xFFFFFFFFu, m, 1));
                    m = fmaxf(m, __shfl_xor_sync(0xFFFFFFFFu, m, 2));
                    if ((lane & 3) == 0) atomicMax(&rowmax[r], fenc(m));
                }
            __syncthreads();
#pragma unroll
            for (int mf = 0; mf < 4; mf++)
#pragma unroll
                for (int h = 0; h < 2; h++) {
                    int r = warpM * 64 + mf * 16 + h * 8 + (lane >> 2);
                    float thr = fdec(rowmax[r]) - MARGIN;
#pragma unroll
                    for (int nf = 0; nf < 8; nf++) {
                        int cb0 = nt * 128 + warpN * 64 + nf * 8 + (lane & 3) * 2;
                        float va = acc[mf][nf][2 * h], vb = acc[mf][nf][2 * h + 1];
                        if (va >= thr) {
                            int p = atomicAdd(&cnt[r], 1);
                            if (p < MAX_CAND) cand[r * MAX_CAND + p] = cb0;
                        }
                        if (vb >= thr) {
                            int p = atomicAdd(&cnt[r], 1);
                            if (p < MAX_CAND) cand[r * MAX_CAND + p] = cb0 + 1;
                        }
                    }
                }
#pragma unroll
            for (int i = 0; i < 4; i++)
#pragma unroll
                for (int jj = 0; jj < 8; jj++)
#pragma unroll
                    for (int k = 0; k < 4; k++) acc[i][jj][k] = 0.0f;
        }
        __syncthreads();
    }

    {
        int row = m0 + tid;
        int c = cnt[tid];
        g_ccnt[row] = c;
        int n = c < MAX_CAND ? c : MAX_CAND;
        for (int i = 0; i < n; i++) g_cand[row * MAX_CAND + i] = cand[tid * MAX_CAND + i];
        if (c > MAX_CAND) {
            int p = atomicAdd(&g_ambig_n, 1);
            if (p < MAX_AMBIG) g_ambig[p] = row;
        }
    }
}

// ------------- K3: fused exact rescore + gather + loss + hist + idx tail ---
// 1024 blocks x 8 warps, each warp handles 4 rows; c==1 fast path.
__global__ void vq_rescore(const float* __restrict__ x, float* __restrict__ out,
                           int out_size) {
    const int lane = threadIdx.x & 31;
    const int wid  = threadIdx.x >> 5;
    const bool write_idx = (out_size >= IDX_OFF + B_ROWS);
    __shared__ double wpart[8];
    double dsum = 0.0;
#pragma unroll 1
    for (int i = 0; i < 4; i++) {
        int row = (blockIdx.x * 8 + wid) * 4 + i;
        int c = g_ccnt[row];
        if (c > MAX_CAND) continue;          // fallback path owns this row
        float xv[8];
#pragma unroll
        for (int jj = 0; jj < 8; jj++) xv[jj] = x[(size_t)row * DIM + lane + jj * 32];
        int bi;
        if (c == 1) {
            bi = g_cand[row * MAX_CAND];
        } else {
            float bv = -3.0e38f; bi = 0x7FFFFFFF;
            for (int k = 0; k < c; k++) {
                int code = g_cand[row * MAX_CAND + k];
                const float* cr = g_cbn + (size_t)code * DIM;
                float s = 0.0f;
#pragma unroll
                for (int jj = 0; jj < 8; jj++) s = fmaf(xv[jj], cr[lane + jj * 32], s);
#pragma unroll
                for (int m = 16; m > 0; m >>= 1) s += __shfl_xor_sync(0xFFFFFFFFu, s, m);
                if (better(s, code, bv, bi)) { bv = s; bi = code; }
            }
        }
        const float* cw = g_cbn + (size_t)bi * DIM;
        float ls = 0.0f;
#pragma unroll
        for (int jj = 0; jj < 8; jj++) {
            float cv = cw[lane + jj * 32];
            float xx = xv[jj];
            out[(size_t)row * DIM + lane + jj * 32] = xx + (cv - xx);
            float d = xx - cv;
            ls = fmaf(d, d, ls);
        }
        dsum += (double)ls;
        if (lane == 0) {
            g_idx[row] = bi;
            atomicAdd(&g_counts[bi], 1);
            if (write_idx) out[IDX_OFF + row] = (float)bi;
        }
    }
#pragma unroll
    for (int m = 16; m > 0; m >>= 1) dsum += __shfl_xor_sync(0xFFFFFFFFu, dsum, m);
    if (lane == 0) wpart[wid] = dsum;
    __syncthreads();
    if (threadIdx.x == 0) {
        double s = 0.0;
        for (int w = 0; w < 8; w++) s += wpart[w];
        g_partials[blockIdx.x] = s;
    }
}

// ------------- K3b: single-kernel fallback full scan (overflow rows) -------
__global__ void vq_rescue(const float* __restrict__ x, float* __restrict__ out,
                          int out_size) {
    const int t = threadIdx.x;
    int n = g_ambig_n; if (n > MAX_AMBIG) n = MAX_AMBIG;
    __shared__ float  xs[256];
    __shared__ float  bvs[256];
    __shared__ int    bis[256];
    __shared__ double dred[256];

    for (int fi = blockIdx.x; fi < n; fi += 64) {
        int row = g_ambig[fi];
        xs[t] = x[(size_t)row * DIM + t];
        __syncthreads();
        float bv = -3.0e38f; int bi = 0x7FFFFFFF;
        for (int code = t; code < K_CODES; code += 256) {
            const float* cr = g_cbn + (size_t)code * DIM;
            float s = 0.0f;
#pragma unroll 8
            for (int d = 0; d < DIM; d++) s = fmaf(xs[d], cr[d], s);
            if (better(s, code, bv, bi)) { bv = s; bi = code; }
        }
        bvs[t] = bv; bis[t] = bi;
        __syncthreads();
        for (int s2 = 128; s2 > 0; s2 >>= 1) {
            if (t < s2 && better(bvs[t + s2], bis[t + s2], bvs[t], bis[t])) {
                bvs[t] = bvs[t + s2]; bis[t] = bis[t + s2];
            }
            __syncthreads();
        }
        bi = bis[0];
        if (t == 0) {
            g_idx[row] = bi;
            atomicAdd(&g_counts[bi], 1);
            if (out_size >= IDX_OFF + B_ROWS) out[IDX_OFF + row] = (float)bi;
        }
        float xx = xs[t];
        float cv = g_cbn[(size_t)bi * DIM + t];
        out[(size_t)row * DIM + t] = xx + (cv - xx);
        float d = xx - cv;
        dred[t] = (double)d * (double)d;
        __syncthreads();
        for (int s2 = 128; s2 > 0; s2 >>= 1) {
            if (t < s2) dred[t] += dred[t + s2];
            __syncthreads();
        }
        if (t == 0) atomicAdd(&g_partials[512 + (fi & 511)], dred[0]);
        __syncthreads();
    }
}

// ------------------------- K4: finalize (scalars only, fp32 log) -----------
__global__ void vq_finalize(float* __restrict__ out, int out_size) {
    const int t = threadIdx.x;               // 1024 threads
    __shared__ double sred[1024];

    // deterministic sum of loss partials
    sred[t] = g_partials[t];
    __syncthreads();
    for (int s = 512; s > 0; s >>= 1) {
        if (t < s) sred[t] += sred[t + s];
        __syncthreads();
    }
    double q = sred[0] / (double)ZQ_ELEMS;
    __syncthreads();

    // entropy of codebook usage (fp32 log, deterministic order)
    double h = 0.0;
#pragma unroll
    for (int k = 0; k < 4; k++) {
        int code = t * 4 + k;
        int c = g_counts[code];
        if (c > 0) {
            float p = (float)c * (1.0f / (float)B_ROWS);
            h -= (double)(p * logf(p));
        }
    }
    sred[t] = h;
    __syncthreads();
    for (int s = 512; s > 0; s >>= 1) {
        if (t < s) sred[t] += sred[t + s];
        __syncthreads();
    }
    double H = sred[0];

    if (t == 0 && out_size >= SCAL_OFF + 5) {
        out[SCAL_OFF + 0] = (float)(1.25 * q - 0.1 * H);
        out[SCAL_OFF + 1] = (float)q;
        out[SCAL_OFF + 2] = (float)q;
        out[SCAL_OFF + 3] = (float)(-H);
        out[SCAL_OFF + 4] = (float)H;
    }
}

// ------------------------- launch ------------------------------------------
extern "C" void kernel_launch(void* const* d_in, const int* in_sizes, int n_in,
                              void* d_out, int out_size) {
    const float* x  = (const float*)d_in[0];
    const float* cb = (const float*)d_in[1];
    if (n_in >= 2 && in_sizes[0] == K_CODES * DIM && in_sizes[1] == B_ROWS * DIM) {
        x  = (const float*)d_in[1];
        cb = (const float*)d_in[0];
    }
    float* out = (float*)d_out;

    static bool attr_set = false;
    if (!attr_set) {
        cudaFuncSetAttribute(vq_mma_argmax,
                             cudaFuncAttributeMaxDynamicSharedMemorySize,
                             (int)SMEM_TOT);
        attr_set = true;
    }

    vq_prep<<<4112, 256>>>(cb);
    vq_mma_argmax<<<B_ROWS / 128, 128, SMEM_TOT>>>(x);
    vq_rescore<<<1024, 256>>>(x, out, out_size);
    vq_rescue<<<64, 256>>>(x, out, out_size);
    vq_finalize<<<1, 1024>>>(out, out_size);
}